// round 1
// baseline (speedup 1.0000x reference)
#include <cuda_runtime.h>

// Problem constants
#define NB    8       // batch
#define NPIX  9216    // H*W = 96*96
#define NHEAD 8
#define NR    64
#define NHD   32

// ---------------------------------------------------------------------------
// Scratch (device globals -- no allocations allowed)
// ---------------------------------------------------------------------------
__device__ float g_RqP[(size_t)NB * 512 * NPIX];   // Rq logits -> probs (in place)
__device__ float g_RkP[(size_t)NB * 512 * NPIX];   // Rk logits -> probs
__device__ float g_G  [(size_t)NB * 2 * 256 * 512]; // G_tgt (which=0), G_src (which=1)
__device__ float g_S  [(size_t)NB * 2 * 512];       // row sums of RqP / RkP
__device__ float g_M  [(size_t)NB * 256 * 512];     // final combined matrix per batch

// ---------------------------------------------------------------------------
// GEMM-A (NN): C[b][m][n] = sum_k W[b][m][k] * X[b][k][n]  (+bias, opt residual)
// Tiles: 128x128, BK=16, 256 threads, 8x8 per thread.
// ---------------------------------------------------------------------------
template<bool RESID>
__global__ __launch_bounds__(256) void gemmA_kernel(
    const float* __restrict__ W, long wstride,
    const float* __restrict__ bias,
    const float* __restrict__ X,
    float* __restrict__ C,
    const float* __restrict__ res,
    const float* __restrict__ alphap,
    int O, int K, int N)
{
    const int b = blockIdx.z;
    const float* Wb = W + (long)b * wstride;
    const float* Xb = X + (long)b * K * N;
    float* Cb = C + (long)b * O * N;
    const float* Rb = RESID ? (res + (long)b * O * N) : nullptr;

    const int tile_n = blockIdx.x * 128;
    const int tile_m = blockIdx.y * 128;

    __shared__ float As[16][132];
    __shared__ float Bs[16][132];

    const int tid = threadIdx.x;
    const int tr = tid >> 4;
    const int tc = tid & 15;

    float acc[8][8];
#pragma unroll
    for (int i = 0; i < 8; i++)
#pragma unroll
        for (int j = 0; j < 8; j++) acc[i][j] = 0.f;

    const int arow = tid >> 2;
    const int akq  = (tid & 3) * 4;
    const int brow = tid >> 5;
    const int bcol = (tid & 31) * 4;

    for (int k0 = 0; k0 < K; k0 += 16) {
        float4 a0 = *(const float4*)(Wb + (long)(tile_m + arow) * K + k0 + akq);
        float4 a1 = *(const float4*)(Wb + (long)(tile_m + arow + 64) * K + k0 + akq);
        float4 b0 = *(const float4*)(Xb + (long)(k0 + brow) * N + tile_n + bcol);
        float4 b1 = *(const float4*)(Xb + (long)(k0 + brow + 8) * N + tile_n + bcol);

        As[akq + 0][arow] = a0.x; As[akq + 1][arow] = a0.y;
        As[akq + 2][arow] = a0.z; As[akq + 3][arow] = a0.w;
        As[akq + 0][arow + 64] = a1.x; As[akq + 1][arow + 64] = a1.y;
        As[akq + 2][arow + 64] = a1.z; As[akq + 3][arow + 64] = a1.w;
        *(float4*)&Bs[brow][bcol]     = b0;
        *(float4*)&Bs[brow + 8][bcol] = b1;
        __syncthreads();

#pragma unroll
        for (int kk = 0; kk < 16; kk++) {
            float a[8], bb[8];
            *(float4*)&a[0]  = *(const float4*)&As[kk][tr * 4];
            *(float4*)&a[4]  = *(const float4*)&As[kk][tr * 4 + 64];
            *(float4*)&bb[0] = *(const float4*)&Bs[kk][tc * 4];
            *(float4*)&bb[4] = *(const float4*)&Bs[kk][tc * 4 + 64];
#pragma unroll
            for (int i = 0; i < 8; i++)
#pragma unroll
                for (int j = 0; j < 8; j++)
                    acc[i][j] += a[i] * bb[j];
        }
        __syncthreads();
    }

    const float alpha = RESID ? *alphap : 0.f;
#pragma unroll
    for (int i = 0; i < 8; i++) {
        const int m = tile_m + tr * 4 + (i < 4 ? i : 60 + i);
        const float bv = bias[m];
        const long base = (long)m * N + tile_n;
#pragma unroll
        for (int jh = 0; jh < 2; jh++) {
            const int n = tc * 4 + jh * 64;
            float4 v;
            v.x = acc[i][jh * 4 + 0] + bv;
            v.y = acc[i][jh * 4 + 1] + bv;
            v.z = acc[i][jh * 4 + 2] + bv;
            v.w = acc[i][jh * 4 + 3] + bv;
            if (RESID) {
                float4 r = *(const float4*)(Rb + base + n);
                v.x = r.x + alpha * v.x;
                v.y = r.y + alpha * v.y;
                v.z = r.z + alpha * v.z;
                v.w = r.w + alpha * v.w;
            }
            *(float4*)(Cb + base + n) = v;
        }
    }
}

// ---------------------------------------------------------------------------
// GEMM-B (NT, deep K): G[b][which][m][j] += sum_n X[b][m][n] * P[b][j][n]
// Tiles: 128x64, BK=16, 256 threads, 8x4 per thread. K split 4-way + atomics.
// ---------------------------------------------------------------------------
__global__ __launch_bounds__(256) void gemmB_kernel(
    const float* __restrict__ X,   // [B,256,N]
    const float* __restrict__ P,   // [B,512,N]
    float* __restrict__ G,         // [B,2,256,512]
    int which, int N)
{
    constexpr int KSPLIT = 4;
    const int bz = blockIdx.z;
    const int b  = bz / KSPLIT;
    const int sp = bz % KSPLIT;
    const int klen = N / KSPLIT;
    const int k0base = sp * klen;

    const float* Xb = X + (long)b * 256 * N;
    const float* Pb = P + (long)b * 512 * N;
    float* Gb = G + ((long)b * 2 + which) * 256 * 512;

    const int tile_m = blockIdx.y * 128;  // c
    const int tile_j = blockIdx.x * 64;   // j

    __shared__ float As[16][132];
    __shared__ float Bs[16][68];

    const int tid = threadIdx.x;
    const int tr = tid >> 4;
    const int tc = tid & 15;

    float acc[8][4];
#pragma unroll
    for (int i = 0; i < 8; i++)
#pragma unroll
        for (int j = 0; j < 4; j++) acc[i][j] = 0.f;

    const int arow = tid >> 2;
    const int akq  = (tid & 3) * 4;

    for (int k0 = k0base; k0 < k0base + klen; k0 += 16) {
        float4 a0 = *(const float4*)(Xb + (long)(tile_m + arow) * N + k0 + akq);
        float4 a1 = *(const float4*)(Xb + (long)(tile_m + arow + 64) * N + k0 + akq);
        float4 p0 = *(const float4*)(Pb + (long)(tile_j + arow) * N + k0 + akq);

        As[akq + 0][arow] = a0.x; As[akq + 1][arow] = a0.y;
        As[akq + 2][arow] = a0.z; As[akq + 3][arow] = a0.w;
        As[akq + 0][arow + 64] = a1.x; As[akq + 1][arow + 64] = a1.y;
        As[akq + 2][arow + 64] = a1.z; As[akq + 3][arow + 64] = a1.w;
        Bs[akq + 0][arow] = p0.x; Bs[akq + 1][arow] = p0.y;
        Bs[akq + 2][arow] = p0.z; Bs[akq + 3][arow] = p0.w;
        __syncthreads();

#pragma unroll
        for (int kk = 0; kk < 16; kk++) {
            float a[8], bb[4];
            *(float4*)&a[0]  = *(const float4*)&As[kk][tr * 4];
            *(float4*)&a[4]  = *(const float4*)&As[kk][tr * 4 + 64];
            *(float4*)&bb[0] = *(const float4*)&Bs[kk][tc * 4];
#pragma unroll
            for (int i = 0; i < 8; i++)
#pragma unroll
                for (int j = 0; j < 4; j++)
                    acc[i][j] += a[i] * bb[j];
        }
        __syncthreads();
    }

#pragma unroll
    for (int i = 0; i < 8; i++) {
        const int m = tile_m + tr * 4 + (i < 4 ? i : 60 + i);
#pragma unroll
        for (int j = 0; j < 4; j++) {
            atomicAdd(&Gb[(long)m * 512 + tile_j + tc * 4 + j], acc[i][j]);
        }
    }
}

// ---------------------------------------------------------------------------
// Channel softmax over 512 channels (in place). One thread per pixel.
// ---------------------------------------------------------------------------
__global__ __launch_bounds__(256) void softmax_ch_kernel(float* __restrict__ P, int N)
{
    const int b = blockIdx.y;
    const int n = blockIdx.x * blockDim.x + threadIdx.x;
    float* Pb = P + (long)b * 512 * N + n;

    float mx = -1e30f;
    for (int j = 0; j < 512; j++) mx = fmaxf(mx, Pb[(long)j * N]);
    float s = 0.f;
    for (int j = 0; j < 512; j++) s += __expf(Pb[(long)j * N] - mx);
    const float inv = 1.f / s;
    for (int j = 0; j < 512; j++) Pb[(long)j * N] = __expf(Pb[(long)j * N] - mx) * inv;
}

// ---------------------------------------------------------------------------
// Row sum: S[b][which][j] = sum_n P[b][j][n]
// ---------------------------------------------------------------------------
__global__ __launch_bounds__(256) void rowsum_kernel(
    const float* __restrict__ P, float* __restrict__ S, int which, int N)
{
    const int b = blockIdx.y, j = blockIdx.x;
    const float* row = P + ((long)b * 512 + j) * N;
    const int tid = threadIdx.x;
    float s = 0.f;
    for (int i = tid; i < N; i += 256) s += row[i];
    __shared__ float red[256];
    red[tid] = s;
    __syncthreads();
    for (int off = 128; off > 0; off >>= 1) {
        if (tid < off) red[tid] += red[tid + off];
        __syncthreads();
    }
    if (tid == 0) S[((long)b * 2 + which) * 512 + j] = red[0];
}

__global__ void zero_kernel(float* p, int n)
{
    int i = blockIdx.x * blockDim.x + threadIdx.x;
    if (i < n) p[i] = 0.f;
}

// ---------------------------------------------------------------------------
// Per-(b,h) region attention: qr/kr/vr from G matrices, softmax attn, vals,
// then M[c][h*64+r] = sum_d Wout[c][h*32+d]*vals[d][r].
// ---------------------------------------------------------------------------
__global__ __launch_bounds__(128) void region_attn_kernel(
    const float* __restrict__ G,    // [B,2,256,512]
    const float* __restrict__ S,    // [B,2,512]
    const float* __restrict__ Wq,  const float* __restrict__ bq,
    const float* __restrict__ Wkv, const float* __restrict__ bkv,
    const float* __restrict__ Wout,
    float* __restrict__ M)          // [B,256,512]
{
    const int h = blockIdx.x, b = blockIdx.y;
    const float* Gt = G + ((long)b * 2 + 0) * 256 * 512;
    const float* Gs = G + ((long)b * 2 + 1) * 256 * 512;
    const float* Sq = S + ((long)b * 2 + 0) * 512;
    const float* Sk = S + ((long)b * 2 + 1) * 512;

    __shared__ float qr[32][64];
    __shared__ float kr[32][64];
    __shared__ float vr[32][64];
    __shared__ float attn[64][65];

    const int tid = threadIdx.x;

    // qr
    for (int idx = tid; idx < 32 * 64; idx += 128) {
        const int d = idx >> 6, r = idx & 63;
        const int row = h * 32 + d, j = h * 64 + r;
        float s0 = 0.f, s1 = 0.f, s2 = 0.f, s3 = 0.f;
        for (int c = 0; c < 256; c += 4) {
            s0 += Wq[row * 256 + c + 0] * Gt[(c + 0) * 512 + j];
            s1 += Wq[row * 256 + c + 1] * Gt[(c + 1) * 512 + j];
            s2 += Wq[row * 256 + c + 2] * Gt[(c + 2) * 512 + j];
            s3 += Wq[row * 256 + c + 3] * Gt[(c + 3) * 512 + j];
        }
        qr[d][r] = (s0 + s1) + (s2 + s3) + bq[row] * Sq[j];
    }
    // kr, vr
    for (int idx = tid; idx < 32 * 64; idx += 128) {
        const int d = idx >> 6, r = idx & 63;
        const int rk = h * 64 + d, rv = h * 64 + 32 + d, j = h * 64 + r;
        float sk0 = 0.f, sk1 = 0.f, sv0 = 0.f, sv1 = 0.f;
        for (int c = 0; c < 256; c += 2) {
            const float g0 = Gs[(c + 0) * 512 + j];
            const float g1 = Gs[(c + 1) * 512 + j];
            sk0 += Wkv[rk * 256 + c + 0] * g0;
            sk1 += Wkv[rk * 256 + c + 1] * g1;
            sv0 += Wkv[rv * 256 + c + 0] * g0;
            sv1 += Wkv[rv * 256 + c + 1] * g1;
        }
        kr[d][r] = sk0 + sk1 + bkv[rk] * Sk[j];
        vr[d][r] = sv0 + sv1 + bkv[rv] * Sk[j];
    }
    __syncthreads();

    // attn logits
    const float scale = rsqrtf((float)NHD);
    for (int idx = tid; idx < 64 * 64; idx += 128) {
        const int qi = idx >> 6, ki = idx & 63;
        float s = 0.f;
#pragma unroll
        for (int d = 0; d < 32; d++) s += qr[d][qi] * kr[d][ki];
        attn[qi][ki] = s * scale;
    }
    __syncthreads();

    // softmax over ki
    if (tid < 64) {
        float mx = -1e30f;
        for (int k = 0; k < 64; k++) mx = fmaxf(mx, attn[tid][k]);
        float s = 0.f;
        for (int k = 0; k < 64; k++) {
            const float e = __expf(attn[tid][k] - mx);
            attn[tid][k] = e;
            s += e;
        }
        const float inv = 1.f / s;
        for (int k = 0; k < 64; k++) attn[tid][k] *= inv;
    }
    __syncthreads();

    // vals (overwrite qr)
    for (int idx = tid; idx < 32 * 64; idx += 128) {
        const int d = idx >> 6, qi = idx & 63;
        float s = 0.f;
#pragma unroll
        for (int k = 0; k < 64; k++) s += vr[d][k] * attn[qi][k];
        qr[d][qi] = s;
    }
    __syncthreads();

    // M
    for (int idx = tid; idx < 256 * 64; idx += 128) {
        const int c = idx >> 6, r = idx & 63;
        float s = 0.f;
#pragma unroll
        for (int d = 0; d < 32; d++) s += Wout[c * 256 + h * 32 + d] * qr[d][r];
        M[((long)b * 256 + c) * 512 + h * 64 + r] = s;
    }
}

// ---------------------------------------------------------------------------
// Launch
// ---------------------------------------------------------------------------
extern "C" void kernel_launch(void* const* d_in, const int* in_sizes, int n_in,
                              void* d_out, int out_size)
{
    const float* src  = (const float*)d_in[0];
    const float* tgt  = (const float*)d_in[1];
    const float* Wq   = (const float*)d_in[2];
    const float* bq   = (const float*)d_in[3];
    const float* Wkv  = (const float*)d_in[4];
    const float* bkv  = (const float*)d_in[5];
    const float* Wrq  = (const float*)d_in[6];
    const float* brq  = (const float*)d_in[7];
    const float* Wrk  = (const float*)d_in[8];
    const float* brk  = (const float*)d_in[9];
    const float* Wout = (const float*)d_in[10];
    const float* bout = (const float*)d_in[11];
    const float* alpha = (const float*)d_in[12];
    float* out = (float*)d_out;

    const int N = NPIX;

    float *RqP, *RkP, *G, *S, *M;
    cudaGetSymbolAddress((void**)&RqP, g_RqP);
    cudaGetSymbolAddress((void**)&RkP, g_RkP);
    cudaGetSymbolAddress((void**)&G,   g_G);
    cudaGetSymbolAddress((void**)&S,   g_S);
    cudaGetSymbolAddress((void**)&M,   g_M);

    // 1) Region logits: RqP = Wrq @ tgt + brq ; RkP = Wrk @ src + brk
    gemmA_kernel<false><<<dim3(N / 128, 512 / 128, NB), 256>>>(
        Wrq, 0, brq, tgt, RqP, nullptr, nullptr, 512, 256, N);
    gemmA_kernel<false><<<dim3(N / 128, 512 / 128, NB), 256>>>(
        Wrk, 0, brk, src, RkP, nullptr, nullptr, 512, 256, N);

    // 2) Channel softmax (512 channels) in place
    softmax_ch_kernel<<<dim3(N / 256, NB), 256>>>(RqP, N);
    softmax_ch_kernel<<<dim3(N / 256, NB), 256>>>(RkP, N);

    // 3) Row sums for bias terms
    rowsum_kernel<<<dim3(512, NB), 256>>>(RqP, S, 0, N);
    rowsum_kernel<<<dim3(512, NB), 256>>>(RkP, S, 1, N);

    // 4) G matrices: G_tgt = tgt @ RqP^T ; G_src = src @ RkP^T
    {
        const int nG = NB * 2 * 256 * 512;
        zero_kernel<<<(nG + 255) / 256, 256>>>(G, nG);
    }
    gemmB_kernel<<<dim3(512 / 64, 256 / 128, NB * 4), 256>>>(tgt, RqP, G, 0, N);
    gemmB_kernel<<<dim3(512 / 64, 256 / 128, NB * 4), 256>>>(src, RkP, G, 1, N);

    // 5) Per-(b,h) small attention -> M
    region_attn_kernel<<<dim3(NHEAD, NB), 128>>>(G, S, Wq, bq, Wkv, bkv, Wout, M);

    // 6) Final: out = tgt + alpha * (M @ RqP + bout)
    gemmA_kernel<true><<<dim3(N / 128, 256 / 128, NB), 256>>>(
        M, (long)256 * 512, bout, RqP, out, tgt, alpha, 256, 512, N);

    (void)in_sizes; (void)n_in; (void)out_size;
}

// round 7
// speedup vs baseline: 2.9565x; 2.9565x over previous
#include <cuda_runtime.h>
#include <cuda_bf16.h>
#include <mma.h>
#include <cstdint>

using namespace nvcuda;

// ---------------------------------------------------------------------------
// Problem constants
// ---------------------------------------------------------------------------
#define NB    8
#define NPIX  9216     // 96*96
#define NREG  512      // R*HEADS
#define NC    256      // channels / E
#define NHEAD 8
#define NHD   32
#define KSPLIT_G 4

// ---------------------------------------------------------------------------
// Scratch (device globals)
// ---------------------------------------------------------------------------
__device__ float         g_L   [(size_t)NB * NPIX * NREG];   // logits raw / final raw (reused)
__device__ __nv_bfloat16 g_PqT [(size_t)NB * NPIX * NREG];
__device__ __nv_bfloat16 g_PkT [(size_t)NB * NPIX * NREG];
__device__ __nv_bfloat16 g_Pq  [(size_t)NB * NREG * NPIX];
__device__ __nv_bfloat16 g_Pk  [(size_t)NB * NREG * NPIX];
__device__ __nv_bfloat16 g_tgt_bf [(size_t)NB * NC * NPIX];
__device__ __nv_bfloat16 g_src_bf [(size_t)NB * NC * NPIX];
__device__ __nv_bfloat16 g_tgtT_bf[(size_t)NB * NPIX * NC];
__device__ __nv_bfloat16 g_srcT_bf[(size_t)NB * NPIX * NC];
__device__ __nv_bfloat16 g_Wrq_bf[NREG * NC];
__device__ __nv_bfloat16 g_Wrk_bf[NREG * NC];
__device__ float         g_Gp  [(size_t)KSPLIT_G * NB * 2 * NC * NREG];  // K-split partials
__device__ float         g_G   [(size_t)NB * 2 * NC * NREG];
__device__ float         g_S   [(size_t)NB * 2 * NREG];
__device__ __nv_bfloat16 g_Mbf [(size_t)NB * NC * NREG];

// ---------------------------------------------------------------------------
// cp.async helpers
// ---------------------------------------------------------------------------
__device__ __forceinline__ uint32_t smem_u32(const void* p) {
    uint32_t a;
    asm("{ .reg .u64 t; cvta.to.shared.u64 t, %1; cvt.u32.u64 %0, t; }"
        : "=r"(a) : "l"(p));
    return a;
}
__device__ __forceinline__ void cp_async16(uint32_t dst, const void* src) {
    asm volatile("cp.async.cg.shared.global [%0], [%1], 16;\n" :: "r"(dst), "l"(src));
}
#define CP_COMMIT()  asm volatile("cp.async.commit_group;\n" ::: "memory")
#define CP_WAIT(n)   asm volatile("cp.async.wait_group %0;\n" :: "n"(n) : "memory")

// ---------------------------------------------------------------------------
// WMMA bf16 GEMM: D[m,n] = sum_k A[m,k]*B[n,k]   (both K-major)
// CTA tile 128x128, BK=32, 256 threads (8 warps, 4x2), warp tile 32x64.
// Raw fp32 store. grid: x = Nrows(B)/128, y = Nrows(A)/128, z = batch*ksplit.
// Per-ksplit output partition offset = partStride.
// LDS=48 (96B row): keeps every fragment base 32B-aligned per WMMA spec.
// ---------------------------------------------------------------------------
__global__ __launch_bounds__(256) void gemm_wmma_kernel(
    const __nv_bfloat16* __restrict__ A, int lda, long strideA,
    const __nv_bfloat16* __restrict__ B, int ldb, long strideB,
    float* __restrict__ C, int ldc, long strideC, long partStride,
    int K, int ksplit)
{
    constexpr int BK = 32;
    constexpr int LDS = 48;   // 96 B row stride: multiple of 32 B (WMMA alignment)

    __shared__ __align__(32) __nv_bfloat16 As[2][128][LDS];
    __shared__ __align__(32) __nv_bfloat16 Bs[2][128][LDS];

    const int tid  = threadIdx.x;
    const int wid  = tid >> 5;
    const int wm   = wid & 3;        // 0..3  (m quadrant, 32 rows)
    const int wn   = wid >> 2;       // 0..1  (n half, 64 cols)

    const int b  = blockIdx.z / ksplit;
    const int sp = blockIdx.z % ksplit;
    const int klen = K / ksplit;
    const int kBeg = sp * klen;
    const int ntiles = klen / BK;

    const __nv_bfloat16* Ab = A + (long)b * strideA + (long)(blockIdx.y * 128) * lda;
    const __nv_bfloat16* Bb = B + (long)b * strideB + (long)(blockIdx.x * 128) * ldb;
    float* Cb = C + (long)b * strideC + (long)sp * partStride;

    // chunk indices for cp.async: 512 16-byte chunks per operand tile
    const int r0 = tid >> 2;          // 0..63
    const int c0 = (tid & 3);         // 0..3 (x8 bf16)

    auto load_stage = [&](int s, int k0) {
#pragma unroll
        for (int half = 0; half < 2; half++) {
            const int row = r0 + half * 64;
            cp_async16(smem_u32(&As[s][row][c0 * 8]),
                       Ab + (long)row * lda + k0 + c0 * 8);
            cp_async16(smem_u32(&Bs[s][row][c0 * 8]),
                       Bb + (long)row * ldb + k0 + c0 * 8);
        }
    };

    wmma::fragment<wmma::accumulator, 16, 16, 16, float> acc[2][4];
#pragma unroll
    for (int i = 0; i < 2; i++)
#pragma unroll
        for (int j = 0; j < 4; j++) wmma::fill_fragment(acc[i][j], 0.0f);

    load_stage(0, kBeg);
    CP_COMMIT();

    for (int kt = 0; kt < ntiles; kt++) {
        if (kt + 1 < ntiles) {
            load_stage((kt + 1) & 1, kBeg + (kt + 1) * BK);
            CP_COMMIT();
            CP_WAIT(1);
        } else {
            CP_WAIT(0);
        }
        __syncthreads();

        const int s = kt & 1;
#pragma unroll
        for (int ks = 0; ks < BK; ks += 16) {
            wmma::fragment<wmma::matrix_a, 16, 16, 16, __nv_bfloat16, wmma::row_major> af[2];
            wmma::fragment<wmma::matrix_b, 16, 16, 16, __nv_bfloat16, wmma::col_major> bf[4];
#pragma unroll
            for (int i = 0; i < 2; i++)
                wmma::load_matrix_sync(af[i], &As[s][wm * 32 + i * 16][ks], LDS);
#pragma unroll
            for (int j = 0; j < 4; j++)
                wmma::load_matrix_sync(bf[j], &Bs[s][wn * 64 + j * 16][ks], LDS);
#pragma unroll
            for (int i = 0; i < 2; i++)
#pragma unroll
                for (int j = 0; j < 4; j++)
                    wmma::mma_sync(acc[i][j], af[i], bf[j], acc[i][j]);
        }
        __syncthreads();
    }

    // raw store
#pragma unroll
    for (int i = 0; i < 2; i++) {
        const int row0 = blockIdx.y * 128 + wm * 32 + i * 16;
#pragma unroll
        for (int j = 0; j < 4; j++) {
            const int col0 = blockIdx.x * 128 + wn * 64 + j * 16;
            wmma::store_matrix_sync(&Cb[(long)row0 * ldc + col0], acc[i][j],
                                    ldc, wmma::mem_row_major);
        }
    }
}

// ---------------------------------------------------------------------------
// fp32 [rows,cols] -> bf16 straight + bf16 transposed
// ---------------------------------------------------------------------------
__global__ __launch_bounds__(256) void convT_kernel(
    const float* __restrict__ X, __nv_bfloat16* __restrict__ Xbf,
    __nv_bfloat16* __restrict__ XT, int rows, int cols)
{
    __shared__ float t[32][33];
    const long bofs = (long)blockIdx.z * rows * cols;
    const int c0 = blockIdx.x * 32, r0 = blockIdx.y * 32;
    const int tx = threadIdx.x & 31, ty = threadIdx.x >> 5;
#pragma unroll
    for (int i = ty; i < 32; i += 8) {
        float v = X[bofs + (long)(r0 + i) * cols + c0 + tx];
        t[i][tx] = v;
        Xbf[bofs + (long)(r0 + i) * cols + c0 + tx] = __float2bfloat16(v);
    }
    __syncthreads();
#pragma unroll
    for (int i = ty; i < 32; i += 8)
        XT[bofs + (long)(c0 + i) * rows + r0 + tx] = __float2bfloat16(t[tx][i]);
}

__global__ __launch_bounds__(256) void convW_kernel(
    const float* __restrict__ W, __nv_bfloat16* __restrict__ Wb, int n)
{
    int i = blockIdx.x * 256 + threadIdx.x;
    if (i < n) Wb[i] = __float2bfloat16(W[i]);
}

// ---------------------------------------------------------------------------
// Row softmax over 512 (+bias fold): L rows (raw logits) -> P^T bf16 rows.
// One warp per row.
// ---------------------------------------------------------------------------
__global__ __launch_bounds__(256) void softmax_rows_kernel(
    const float* __restrict__ L, const float* __restrict__ bias,
    __nv_bfloat16* __restrict__ PT)
{
    const long row = (long)blockIdx.x * 8 + (threadIdx.x >> 5);
    const int lane = threadIdx.x & 31;
    const float* rp = L + row * NREG;
    float v[16];
    float mx = -1e30f;
#pragma unroll
    for (int i = 0; i < 16; i++) {
        v[i] = rp[lane + i * 32] + bias[lane + i * 32];
        mx = fmaxf(mx, v[i]);
    }
#pragma unroll
    for (int o = 16; o > 0; o >>= 1) mx = fmaxf(mx, __shfl_xor_sync(0xffffffffu, mx, o));
    float s = 0.f;
#pragma unroll
    for (int i = 0; i < 16; i++) { v[i] = __expf(v[i] - mx); s += v[i]; }
#pragma unroll
    for (int o = 16; o > 0; o >>= 1) s += __shfl_xor_sync(0xffffffffu, s, o);
    const float inv = 1.f / s;
    __nv_bfloat16* pp = PT + row * NREG;
#pragma unroll
    for (int i = 0; i < 16; i++) pp[lane + i * 32] = __float2bfloat16(v[i] * inv);
}

// ---------------------------------------------------------------------------
// bf16 transpose: PT [NPIX,512] -> P [512,NPIX] per batch
// ---------------------------------------------------------------------------
__global__ __launch_bounds__(256) void transpose_bf_kernel(
    const __nv_bfloat16* __restrict__ PT, __nv_bfloat16* __restrict__ P)
{
    __shared__ __nv_bfloat16 t[32][33];
    const long bi = (long)blockIdx.z * NPIX * NREG;
    const int j0 = blockIdx.x * 32, n0 = blockIdx.y * 32;
    const int tx = threadIdx.x & 31, ty = threadIdx.x >> 5;
#pragma unroll
    for (int i = ty; i < 32; i += 8)
        t[i][tx] = PT[bi + (long)(n0 + i) * NREG + j0 + tx];
    __syncthreads();
#pragma unroll
    for (int i = ty; i < 32; i += 8)
        P[bi + (long)(j0 + i) * NPIX + n0 + tx] = t[tx][i];
}

// ---------------------------------------------------------------------------
// Row sums of P (bf16) -> S[b][which][j]
// ---------------------------------------------------------------------------
__global__ __launch_bounds__(256) void rowsum_kernel(
    const __nv_bfloat16* __restrict__ P, float* __restrict__ S, int which)
{
    const int b = blockIdx.y, j = blockIdx.x;
    const __nv_bfloat16* row = P + ((long)b * NREG + j) * NPIX;
    const int tid = threadIdx.x;
    float s = 0.f;
    for (int i = tid; i < NPIX; i += 256) s += __bfloat162float(row[i]);
    __shared__ float red[256];
    red[tid] = s;
    __syncthreads();
    for (int off = 128; off > 0; off >>= 1) {
        if (tid < off) red[tid] += red[tid + off];
        __syncthreads();
    }
    if (tid == 0) S[((long)b * 2 + which) * NREG + j] = red[0];
}

// ---------------------------------------------------------------------------
// Reduce KSPLIT_G partials: G[i] = sum_sp Gp[sp][i]
// ---------------------------------------------------------------------------
__global__ __launch_bounds__(256) void reduceG_kernel(
    const float* __restrict__ Gp, float* __restrict__ G, int n, long part)
{
    int i = blockIdx.x * 256 + threadIdx.x;
    if (i < n)
        G[i] = Gp[i] + Gp[i + part] + Gp[i + 2 * part] + Gp[i + 3 * part];
}

// ---------------------------------------------------------------------------
// Final elementwise: out[b,c,n] = tgt[b,c,n] + alpha*(raw[b,c,n] + bout[c])
// float4-vectorized.
// ---------------------------------------------------------------------------
__global__ __launch_bounds__(256) void final_ep_kernel(
    const float* __restrict__ raw, const float* __restrict__ tgt,
    const float* __restrict__ bout, const float* __restrict__ alphap,
    float* __restrict__ out)
{
    const long i4 = (long)blockIdx.x * 256 + threadIdx.x;
    const long base = i4 * 4;
    const int c = (int)((base / NPIX) % NC);
    const float alpha = *alphap;
    const float bv = bout[c];
    float4 r = *(const float4*)(raw + base);
    float4 t = *(const float4*)(tgt + base);
    float4 o;
    o.x = t.x + alpha * (r.x + bv);
    o.y = t.y + alpha * (r.y + bv);
    o.z = t.z + alpha * (r.z + bv);
    o.w = t.w + alpha * (r.w + bv);
    *(float4*)(out + base) = o;
}

// ---------------------------------------------------------------------------
// Per-(b,h) region attention -> M (bf16)
// ---------------------------------------------------------------------------
__global__ __launch_bounds__(128) void region_attn_kernel(
    const float* __restrict__ G, const float* __restrict__ S,
    const float* __restrict__ Wq,  const float* __restrict__ bq,
    const float* __restrict__ Wkv, const float* __restrict__ bkv,
    const float* __restrict__ Wout,
    __nv_bfloat16* __restrict__ M)
{
    const int h = blockIdx.x, b = blockIdx.y;
    const float* Gt = G + ((long)b * 2 + 0) * NC * NREG;
    const float* Gs = G + ((long)b * 2 + 1) * NC * NREG;
    const float* Sq = S + ((long)b * 2 + 0) * NREG;
    const float* Sk = S + ((long)b * 2 + 1) * NREG;

    __shared__ float qr[32][64];
    __shared__ float kr[32][64];
    __shared__ float vr[32][64];
    __shared__ float attn[64][65];

    const int tid = threadIdx.x;

    for (int idx = tid; idx < 32 * 64; idx += 128) {
        const int d = idx >> 6, r = idx & 63;
        const int row = h * 32 + d, j = h * 64 + r;
        float s0 = 0.f, s1 = 0.f;
        for (int c = 0; c < 256; c += 2) {
            s0 += Wq[row * 256 + c + 0] * Gt[(c + 0) * NREG + j];
            s1 += Wq[row * 256 + c + 1] * Gt[(c + 1) * NREG + j];
        }
        qr[d][r] = s0 + s1 + bq[row] * Sq[j];
    }
    for (int idx = tid; idx < 32 * 64; idx += 128) {
        const int d = idx >> 6, r = idx & 63;
        const int rk = h * 64 + d, rv = h * 64 + 32 + d, j = h * 64 + r;
        float sk = 0.f, sv = 0.f;
        for (int c = 0; c < 256; c++) {
            const float g = Gs[c * NREG + j];
            sk += Wkv[rk * 256 + c] * g;
            sv += Wkv[rv * 256 + c] * g;
        }
        kr[d][r] = sk + bkv[rk] * Sk[j];
        vr[d][r] = sv + bkv[rv] * Sk[j];
    }
    __syncthreads();

    const float scale = rsqrtf((float)NHD);
    for (int idx = tid; idx < 64 * 64; idx += 128) {
        const int qi = idx >> 6, ki = idx & 63;
        float s = 0.f;
#pragma unroll
        for (int d = 0; d < 32; d++) s += qr[d][qi] * kr[d][ki];
        attn[qi][ki] = s * scale;
    }
    __syncthreads();

    if (tid < 64) {
        float mx = -1e30f;
        for (int k = 0; k < 64; k++) mx = fmaxf(mx, attn[tid][k]);
        float s = 0.f;
        for (int k = 0; k < 64; k++) {
            const float e = __expf(attn[tid][k] - mx);
            attn[tid][k] = e;
            s += e;
        }
        const float inv = 1.f / s;
        for (int k = 0; k < 64; k++) attn[tid][k] *= inv;
    }
    __syncthreads();

    for (int idx = tid; idx < 32 * 64; idx += 128) {
        const int d = idx >> 6, qi = idx & 63;
        float s = 0.f;
#pragma unroll
        for (int k = 0; k < 64; k++) s += vr[d][k] * attn[qi][k];
        qr[d][qi] = s;
    }
    __syncthreads();

    for (int idx = tid; idx < 256 * 64; idx += 128) {
        const int c = idx >> 6, r = idx & 63;
        float s = 0.f;
#pragma unroll
        for (int d = 0; d < 32; d++) s += Wout[c * 256 + h * 32 + d] * qr[d][r];
        M[((long)b * NC + c) * NREG + h * 64 + r] = __float2bfloat16(s);
    }
}

// ---------------------------------------------------------------------------
// Launch
// ---------------------------------------------------------------------------
extern "C" void kernel_launch(void* const* d_in, const int* in_sizes, int n_in,
                              void* d_out, int out_size)
{
    const float* src  = (const float*)d_in[0];
    const float* tgt  = (const float*)d_in[1];
    const float* Wq   = (const float*)d_in[2];
    const float* bq   = (const float*)d_in[3];
    const float* Wkv  = (const float*)d_in[4];
    const float* bkv  = (const float*)d_in[5];
    const float* Wrq  = (const float*)d_in[6];
    const float* brq  = (const float*)d_in[7];
    const float* Wrk  = (const float*)d_in[8];
    const float* brk  = (const float*)d_in[9];
    const float* Wout = (const float*)d_in[10];
    const float* bout = (const float*)d_in[11];
    const float* alpha = (const float*)d_in[12];
    float* out = (float*)d_out;

    float *L, *Gp, *G, *S;
    __nv_bfloat16 *PqT, *PkT, *Pq, *Pk, *tgt_bf, *src_bf, *tgtT, *srcT, *Wrq_bf, *Wrk_bf, *Mbf;
    cudaGetSymbolAddress((void**)&L,      g_L);
    cudaGetSymbolAddress((void**)&PqT,    g_PqT);
    cudaGetSymbolAddress((void**)&PkT,    g_PkT);
    cudaGetSymbolAddress((void**)&Pq,     g_Pq);
    cudaGetSymbolAddress((void**)&Pk,     g_Pk);
    cudaGetSymbolAddress((void**)&tgt_bf, g_tgt_bf);
    cudaGetSymbolAddress((void**)&src_bf, g_src_bf);
    cudaGetSymbolAddress((void**)&tgtT,   g_tgtT_bf);
    cudaGetSymbolAddress((void**)&srcT,   g_srcT_bf);
    cudaGetSymbolAddress((void**)&Wrq_bf, g_Wrq_bf);
    cudaGetSymbolAddress((void**)&Wrk_bf, g_Wrk_bf);
    cudaGetSymbolAddress((void**)&Gp,     g_Gp);
    cudaGetSymbolAddress((void**)&G,      g_G);
    cudaGetSymbolAddress((void**)&S,      g_S);
    cudaGetSymbolAddress((void**)&Mbf,    g_Mbf);

    const long GTOT = (long)NB * 2 * NC * NREG;

    // 0) conversions
    convT_kernel<<<dim3(NPIX / 32, NC / 32, NB), 256>>>(tgt, tgt_bf, tgtT, NC, NPIX);
    convT_kernel<<<dim3(NPIX / 32, NC / 32, NB), 256>>>(src, src_bf, srcT, NC, NPIX);
    convW_kernel<<<(NREG * NC + 255) / 256, 256>>>(Wrq, Wrq_bf, NREG * NC);
    convW_kernel<<<(NREG * NC + 255) / 256, 256>>>(Wrk, Wrk_bf, NREG * NC);

    // 1q) raw Lq[n,j] = tgtT . Wrq^T ; softmax(+brq) -> PqT ; transpose -> Pq
    gemm_wmma_kernel<<<dim3(NREG / 128, NPIX / 128, NB), 256>>>(
        tgtT, NC, (long)NPIX * NC, Wrq_bf, NC, 0,
        L, NREG, (long)NPIX * NREG, 0, NC, 1);
    softmax_rows_kernel<<<NB * NPIX / 8, 256>>>(L, brq, PqT);
    transpose_bf_kernel<<<dim3(NREG / 32, NPIX / 32, NB), 256>>>(PqT, Pq);
    rowsum_kernel<<<dim3(NREG, NB), 256>>>(Pq, S, 0);

    // 1k) same for k
    gemm_wmma_kernel<<<dim3(NREG / 128, NPIX / 128, NB), 256>>>(
        srcT, NC, (long)NPIX * NC, Wrk_bf, NC, 0,
        L, NREG, (long)NPIX * NREG, 0, NC, 1);
    softmax_rows_kernel<<<NB * NPIX / 8, 256>>>(L, brk, PkT);
    transpose_bf_kernel<<<dim3(NREG / 32, NPIX / 32, NB), 256>>>(PkT, Pk);
    rowsum_kernel<<<dim3(NREG, NB), 256>>>(Pk, S, 1);

    // 2) G matrices: K-split partials into Gp, then reduce
    gemm_wmma_kernel<<<dim3(NREG / 128, NC / 128, NB * KSPLIT_G), 256>>>(
        tgt_bf, NPIX, (long)NC * NPIX, Pq, NPIX, (long)NREG * NPIX,
        Gp, NREG, (long)2 * NC * NREG, GTOT, NPIX, KSPLIT_G);
    gemm_wmma_kernel<<<dim3(NREG / 128, NC / 128, NB * KSPLIT_G), 256>>>(
        src_bf, NPIX, (long)NC * NPIX, Pk, NPIX, (long)NREG * NPIX,
        Gp + (long)NC * NREG, NREG, (long)2 * NC * NREG, GTOT, NPIX, KSPLIT_G);
    reduceG_kernel<<<(int)((GTOT + 255) / 256), 256>>>(Gp, G, (int)GTOT, GTOT);

    // 3) small attention -> M (bf16)
    region_attn_kernel<<<dim3(NHEAD, NB), 128>>>(G, S, Wq, bq, Wkv, bkv, Wout, Mbf);

    // 4) raw final = M . Pq  (via PqT as K-major B), then elementwise residual
    gemm_wmma_kernel<<<dim3(NPIX / 128, NC / 128, NB), 256>>>(
        Mbf, NREG, (long)NC * NREG, PqT, NREG, (long)NPIX * NREG,
        L, NPIX, (long)NC * NPIX, 0, NREG, 1);
    final_ep_kernel<<<(int)((long)NB * NC * NPIX / 4 / 256), 256>>>(
        L, tgt, bout, alpha, out);

    (void)in_sizes; (void)n_in; (void)out_size;
}